// round 1
// baseline (speedup 1.0000x reference)
#include <cuda_runtime.h>
#include <cuda_bf16.h>
#include <math.h>

// ---------------------------------------------------------------------------
// ACM-GCN on GB300: 2 layers.
//   per layer: hl = h@Wl, hh = h@Wh, hm = relu(h@Wm)   (dense GEMMs)
//              low  = relu(inv_deg * segsum(hl[col] by row))
//              high = relu(hh - inv_deg * segsum(hh[col] by row))
//              logits -> sigmoid -> @att(3x3) -> /3 -> softmax
//              out = 3*(a0*low + a1*high + a2*hm)  (+relu between layers)
// Strategy: build CSR once per call (counting sort), warp-per-row fused
// spmm+attention epilogue; register-tiled fp32 SGEMM for the dense parts.
// ---------------------------------------------------------------------------

#define MAXN 100000
#define MAXE 1600000

__device__ int   g_deg[MAXN];
__device__ int   g_fill[MAXN];
__device__ int   g_rowptr[MAXN + 1];
__device__ int   g_col[MAXE];
__device__ float g_hl[(size_t)MAXN * 128];
__device__ float g_hh[(size_t)MAXN * 128];
__device__ float g_hm[(size_t)MAXN * 128];
__device__ float g_fea[(size_t)MAXN * 128];

// --------------------------- CSR construction -----------------------------

__global__ void zero_kernel(int* deg, int* fill, int n) {
    int i = blockIdx.x * blockDim.x + threadIdx.x;
    if (i < n) { deg[i] = 0; fill[i] = 0; }
}

__global__ void deg_kernel(const int* __restrict__ row, int* deg, int E) {
    int e = blockIdx.x * blockDim.x + threadIdx.x;
    if (e < E) atomicAdd(&deg[row[e]], 1);
}

__global__ void scan_kernel(const int* __restrict__ deg, int* __restrict__ rowptr, int n) {
    __shared__ int wsum[32];
    __shared__ int carry;
    int tid = threadIdx.x, lane = tid & 31, w = tid >> 5;
    if (tid == 0) carry = 0;
    __syncthreads();
    for (int base = 0; base < n; base += 1024) {
        int i = base + tid;
        int v = (i < n) ? deg[i] : 0;
        int x = v;
        #pragma unroll
        for (int o = 1; o < 32; o <<= 1) {
            int y = __shfl_up_sync(0xffffffffu, x, o);
            if (lane >= o) x += y;
        }
        if (lane == 31) wsum[w] = x;
        __syncthreads();
        if (w == 0) {
            int t = wsum[lane];
            #pragma unroll
            for (int o = 1; o < 32; o <<= 1) {
                int y = __shfl_up_sync(0xffffffffu, t, o);
                if (lane >= o) t += y;
            }
            wsum[lane] = t;
        }
        __syncthreads();
        int off = carry + (w > 0 ? wsum[w - 1] : 0);
        if (i < n) rowptr[i] = off + x - v;
        int blocktotal = wsum[31];
        __syncthreads();
        if (tid == 0) carry += blocktotal;
        __syncthreads();
    }
    if (threadIdx.x == 0) rowptr[n] = carry;
}

__global__ void scatter_kernel(const int* __restrict__ row, const int* __restrict__ colsrc,
                               const int* __restrict__ rowptr, int* fill,
                               int* __restrict__ colout, int E) {
    int e = blockIdx.x * blockDim.x + threadIdx.x;
    if (e < E) {
        int r = row[e];
        int p = rowptr[r] + atomicAdd(&fill[r], 1);
        colout[p] = colsrc[e];
    }
}

// ------------------------------ SGEMM --------------------------------------
// C[y] = A @ B[y]; relu applied when blockIdx.y == 2 (the mlp branch).
// A: M x K row-major, B: K x N row-major.

template <int BM, int BN, int BK, int TM, int TN>
__global__ __launch_bounds__((BM / TM) * (BN / TN))
void sgemm3(const float* __restrict__ A,
            const float* __restrict__ B0, const float* __restrict__ B1, const float* __restrict__ B2,
            float* __restrict__ C0, float* __restrict__ C1, float* __restrict__ C2,
            int M, int K, int Nn) {
    constexpr int NT = (BM / TM) * (BN / TN);
    __shared__ __align__(16) float As[BK][BM];
    __shared__ __align__(16) float Bs[BK][BN];

    const int tid = threadIdx.x;
    const float* B = (blockIdx.y == 0) ? B0 : (blockIdx.y == 1) ? B1 : B2;
    float* C = (blockIdx.y == 0) ? C0 : (blockIdx.y == 1) ? C1 : C2;
    const bool relu = (blockIdx.y == 2);

    const int rowBase = blockIdx.x * BM;
    const int tc = tid % (BN / TN);
    const int tr = tid / (BN / TN);

    float acc[TM][TN];
    #pragma unroll
    for (int m = 0; m < TM; m++)
        #pragma unroll
        for (int nn = 0; nn < TN; nn++) acc[m][nn] = 0.0f;

    for (int k0 = 0; k0 < K; k0 += BK) {
        // load A tile (transposed into As[k][m])
        #pragma unroll
        for (int i = tid * 4; i < BM * BK; i += NT * 4) {
            int r = i / BK, k = i % BK;
            int gr = rowBase + r;
            float4 v = make_float4(0.f, 0.f, 0.f, 0.f);
            if (gr < M) v = *(const float4*)(A + (size_t)gr * K + k0 + k);
            As[k + 0][r] = v.x; As[k + 1][r] = v.y; As[k + 2][r] = v.z; As[k + 3][r] = v.w;
        }
        // load B tile
        #pragma unroll
        for (int i = tid * 4; i < BK * BN; i += NT * 4) {
            int k = i / BN, n = i % BN;
            *(float4*)&Bs[k][n] = *(const float4*)(B + (size_t)(k0 + k) * Nn + n);
        }
        __syncthreads();

        #pragma unroll
        for (int k = 0; k < BK; k++) {
            float ra[TM], rb[TN];
            #pragma unroll
            for (int m = 0; m < TM; m += 4)
                *(float4*)&ra[m] = *(const float4*)&As[k][tr * TM + m];
            #pragma unroll
            for (int nn = 0; nn < TN; nn += 4)
                *(float4*)&rb[nn] = *(const float4*)&Bs[k][tc * TN + nn];
            #pragma unroll
            for (int m = 0; m < TM; m++)
                #pragma unroll
                for (int nn = 0; nn < TN; nn++)
                    acc[m][nn] = fmaf(ra[m], rb[nn], acc[m][nn]);
        }
        __syncthreads();
    }

    #pragma unroll
    for (int m = 0; m < TM; m++) {
        int gr = rowBase + tr * TM + m;
        if (gr < M) {
            #pragma unroll
            for (int n0 = 0; n0 < TN; n0 += 4) {
                float4 v;
                v.x = acc[m][n0 + 0]; v.y = acc[m][n0 + 1];
                v.z = acc[m][n0 + 2]; v.w = acc[m][n0 + 3];
                if (relu) {
                    v.x = fmaxf(v.x, 0.f); v.y = fmaxf(v.y, 0.f);
                    v.z = fmaxf(v.z, 0.f); v.w = fmaxf(v.w, 0.f);
                }
                *(float4*)(C + (size_t)gr * Nn + tc * TN + n0) = v;
            }
        }
    }
}

// ------------------- fused spmm + attention epilogue -----------------------
// One warp per node row. D = feature dim (128 or 64).

template <int D, bool FRELU>
__global__ __launch_bounds__(256)
void acm_fuse(const float* __restrict__ hl, const float* __restrict__ hh,
              const float* __restrict__ hm,
              const int* __restrict__ rowptr, const int* __restrict__ col,
              const float* __restrict__ vl, const float* __restrict__ vh,
              const float* __restrict__ vm, const float* __restrict__ av,
              float* __restrict__ out, int n) {
    constexpr int V = D / 32;
    int gw = (blockIdx.x * blockDim.x + threadIdx.x) >> 5;
    if (gw >= n) return;
    const int lane = threadIdx.x & 31;
    const int s = rowptr[gw], e = rowptr[gw + 1];

    float accl[V], acch[V];
    #pragma unroll
    for (int i = 0; i < V; i++) { accl[i] = 0.f; acch[i] = 0.f; }

    for (int base = s; base < e; base += 32) {
        int idx = base + lane;
        int c = (idx < e) ? col[idx] : 0;
        int cnt = min(32, e - base);
        for (int k = 0; k < cnt; k++) {
            int cc = __shfl_sync(0xffffffffu, c, k);
            const float* pl = hl + (size_t)cc * D + lane * V;
            const float* ph = hh + (size_t)cc * D + lane * V;
            if constexpr (V == 4) {
                float4 a = *(const float4*)pl;
                accl[0] += a.x; accl[1] += a.y; accl[2] += a.z; accl[3] += a.w;
                float4 b = *(const float4*)ph;
                acch[0] += b.x; acch[1] += b.y; acch[2] += b.z; acch[3] += b.w;
            } else {
                float2 a = *(const float2*)pl;
                accl[0] += a.x; accl[1] += a.y;
                float2 b = *(const float2*)ph;
                acch[0] += b.x; acch[1] += b.y;
            }
        }
    }

    const float inv = (e > s) ? 1.0f / (float)(e - s) : 0.0f;

    float low[V], high[V], mlp[V];
    {
        const float* ph = hh + (size_t)gw * D + lane * V;
        const float* pm = hm + (size_t)gw * D + lane * V;
        if constexpr (V == 4) {
            float4 b = *(const float4*)ph;
            float4 m = *(const float4*)pm;
            float hrow[4] = {b.x, b.y, b.z, b.w};
            float mrow[4] = {m.x, m.y, m.z, m.w};
            #pragma unroll
            for (int i = 0; i < 4; i++) {
                low[i]  = fmaxf(inv * accl[i], 0.f);
                high[i] = fmaxf(hrow[i] - inv * acch[i], 0.f);
                mlp[i]  = mrow[i];
            }
        } else {
            float2 b = *(const float2*)ph;
            float2 m = *(const float2*)pm;
            float hrow[2] = {b.x, b.y};
            float mrow[2] = {m.x, m.y};
            #pragma unroll
            for (int i = 0; i < 2; i++) {
                low[i]  = fmaxf(inv * accl[i], 0.f);
                high[i] = fmaxf(hrow[i] - inv * acch[i], 0.f);
                mlp[i]  = mrow[i];
            }
        }
    }

    // dot products with v_low / v_high / v_mlp
    float dl = 0.f, dh = 0.f, dm = 0.f;
    #pragma unroll
    for (int i = 0; i < V; i++) {
        dl += low[i]  * vl[lane * V + i];
        dh += high[i] * vh[lane * V + i];
        dm += mlp[i]  * vm[lane * V + i];
    }
    #pragma unroll
    for (int o = 16; o > 0; o >>= 1) {
        dl += __shfl_xor_sync(0xffffffffu, dl, o);
        dh += __shfl_xor_sync(0xffffffffu, dh, o);
        dm += __shfl_xor_sync(0xffffffffu, dm, o);
    }

    float sl = 1.0f / (1.0f + __expf(-dl));
    float sh = 1.0f / (1.0f + __expf(-dh));
    float sm = 1.0f / (1.0f + __expf(-dm));

    float t0 = (sl * av[0] + sh * av[3] + sm * av[6]) * (1.0f / 3.0f);
    float t1 = (sl * av[1] + sh * av[4] + sm * av[7]) * (1.0f / 3.0f);
    float t2 = (sl * av[2] + sh * av[5] + sm * av[8]) * (1.0f / 3.0f);
    float mx = fmaxf(t0, fmaxf(t1, t2));
    float w0 = __expf(t0 - mx), w1 = __expf(t1 - mx), w2 = __expf(t2 - mx);
    float wsum = w0 + w1 + w2;
    float a0 = 3.0f * w0 / wsum, a1 = 3.0f * w1 / wsum, a2 = 3.0f * w2 / wsum;

    float* po = out + (size_t)gw * D + lane * V;
    if constexpr (V == 4) {
        float4 o4;
        float tmp[4];
        #pragma unroll
        for (int i = 0; i < 4; i++) {
            float v = a0 * low[i] + a1 * high[i] + a2 * mlp[i];
            if (FRELU) v = fmaxf(v, 0.f);
            tmp[i] = v;
        }
        o4.x = tmp[0]; o4.y = tmp[1]; o4.z = tmp[2]; o4.w = tmp[3];
        *(float4*)po = o4;
    } else {
        float2 o2;
        float v0 = a0 * low[0] + a1 * high[0] + a2 * mlp[0];
        float v1 = a0 * low[1] + a1 * high[1] + a2 * mlp[1];
        if (FRELU) { v0 = fmaxf(v0, 0.f); v1 = fmaxf(v1, 0.f); }
        o2.x = v0; o2.y = v1;
        *(float2*)po = o2;
    }
}

// ------------------------------ launch -------------------------------------

extern "C" void kernel_launch(void* const* d_in, const int* in_sizes, int n_in,
                              void* d_out, int out_size) {
    const float* x    = (const float*)d_in[0];
    const int*   ei   = (const int*)d_in[1];
    const float* Wl1  = (const float*)d_in[2];
    const float* Wh1  = (const float*)d_in[3];
    const float* Wm1  = (const float*)d_in[4];
    const float* vl1  = (const float*)d_in[5];
    const float* vh1  = (const float*)d_in[6];
    const float* vm1  = (const float*)d_in[7];
    const float* av1  = (const float*)d_in[8];
    const float* Wl2  = (const float*)d_in[9];
    const float* Wh2  = (const float*)d_in[10];
    const float* Wm2  = (const float*)d_in[11];
    const float* vl2  = (const float*)d_in[12];
    const float* vh2  = (const float*)d_in[13];
    const float* vm2  = (const float*)d_in[14];
    const float* av2  = (const float*)d_in[15];

    const int n = in_sizes[0] / 128;   // N nodes (F=128)
    const int E = in_sizes[1] / 2;     // edges
    const int* row = ei;
    const int* colsrc = ei + E;

    int *deg, *fill, *rowptr, *col;
    float *hl, *hh, *hm, *fea;
    cudaGetSymbolAddress((void**)&deg, g_deg);
    cudaGetSymbolAddress((void**)&fill, g_fill);
    cudaGetSymbolAddress((void**)&rowptr, g_rowptr);
    cudaGetSymbolAddress((void**)&col, g_col);
    cudaGetSymbolAddress((void**)&hl, g_hl);
    cudaGetSymbolAddress((void**)&hh, g_hh);
    cudaGetSymbolAddress((void**)&hm, g_hm);
    cudaGetSymbolAddress((void**)&fea, g_fea);

    float* out = (float*)d_out;

    // CSR build
    zero_kernel<<<(n + 255) / 256, 256>>>(deg, fill, n);
    deg_kernel<<<(E + 255) / 256, 256>>>(row, deg, E);
    scan_kernel<<<1, 1024>>>(deg, rowptr, n);
    scatter_kernel<<<(E + 255) / 256, 256>>>(row, colsrc, rowptr, fill, col, E);

    // layer 1: x (n x 128) @ {Wl1,Wh1,Wm1} (128 x 128)
    {
        dim3 grid((n + 127) / 128, 3);
        sgemm3<128, 128, 8, 8, 8><<<grid, 256>>>(x, Wl1, Wh1, Wm1, hl, hh, hm, n, 128, 128);
    }
    acm_fuse<128, true><<<(n + 7) / 8, 256>>>(hl, hh, hm, rowptr, col,
                                              vl1, vh1, vm1, av1, fea, n);

    // layer 2: fea (n x 128) @ {Wl2,Wh2,Wm2} (128 x 64)
    {
        dim3 grid((n + 127) / 128, 3);
        sgemm3<128, 64, 8, 8, 4><<<grid, 256>>>(fea, Wl2, Wh2, Wm2, hl, hh, hm, n, 128, 64);
    }
    acm_fuse<64, false><<<(n + 7) / 8, 256>>>(hl, hh, hm, rowptr, col,
                                              vl2, vh2, vm2, av2, out, n);
}

// round 3
// speedup vs baseline: 1.2948x; 1.2948x over previous
#include <cuda_runtime.h>
#include <cuda_bf16.h>
#include <cstdint>
#include <math.h>

// ---------------------------------------------------------------------------
// ACM-GCN on GB300, round 3: dense GEMMs via mma.sync (HMMA) split-bf16
// (tcgen05 is unusable: harness ptxas targets sm_103 without the 'a' suffix).
// A@B = Ahi@Bhi + Ahi@Blo + Alo@Bhi, fp32 accumulate.
// ---------------------------------------------------------------------------

#define MAXN 100000
#define MAXE 1600000

__device__ int   g_deg[MAXN];
__device__ int   g_fill[MAXN];
__device__ int   g_rowptr[MAXN + 1];
__device__ int   g_col[MAXE];
__device__ float g_hl[(size_t)MAXN * 128];
__device__ float g_hh[(size_t)MAXN * 128];
__device__ float g_hm[(size_t)MAXN * 128];
__device__ float g_fea[(size_t)MAXN * 128];
__device__ __nv_bfloat16 g_ahi[(size_t)MAXN * 128];
__device__ __nv_bfloat16 g_alo[(size_t)MAXN * 128];
__device__ __nv_bfloat16 g_wthi[3 * 128 * 128];
__device__ __nv_bfloat16 g_wtlo[3 * 128 * 128];

__device__ __forceinline__ uint32_t smem_u32(const void* p) {
    uint32_t a;
    asm("{ .reg .u64 t; cvta.to.shared.u64 t, %1; cvt.u32.u64 %0, t; }"
        : "=r"(a) : "l"(p));
    return a;
}

// --------------------------- CSR construction -----------------------------

__global__ void zero_kernel(int* deg, int* fill, int n) {
    int i = blockIdx.x * blockDim.x + threadIdx.x;
    if (i < n) { deg[i] = 0; fill[i] = 0; }
}

__global__ void deg_kernel(const int* __restrict__ row, int* deg, int E) {
    int e = blockIdx.x * blockDim.x + threadIdx.x;
    if (e < E) atomicAdd(&deg[row[e]], 1);
}

__global__ void scan_kernel(const int* __restrict__ deg, int* __restrict__ rowptr, int n) {
    __shared__ int wsum[32];
    __shared__ int carry;
    int tid = threadIdx.x, lane = tid & 31, w = tid >> 5;
    if (tid == 0) carry = 0;
    __syncthreads();
    for (int base = 0; base < n; base += 1024) {
        int i = base + tid;
        int v = (i < n) ? deg[i] : 0;
        int x = v;
        #pragma unroll
        for (int o = 1; o < 32; o <<= 1) {
            int y = __shfl_up_sync(0xffffffffu, x, o);
            if (lane >= o) x += y;
        }
        if (lane == 31) wsum[w] = x;
        __syncthreads();
        if (w == 0) {
            int t = wsum[lane];
            #pragma unroll
            for (int o = 1; o < 32; o <<= 1) {
                int y = __shfl_up_sync(0xffffffffu, t, o);
                if (lane >= o) t += y;
            }
            wsum[lane] = t;
        }
        __syncthreads();
        int off = carry + (w > 0 ? wsum[w - 1] : 0);
        if (i < n) rowptr[i] = off + x - v;
        int blocktotal = wsum[31];
        __syncthreads();
        if (tid == 0) carry += blocktotal;
        __syncthreads();
    }
    if (threadIdx.x == 0) rowptr[n] = carry;
}

__global__ void scatter_kernel(const int* __restrict__ row, const int* __restrict__ colsrc,
                               const int* __restrict__ rowptr, int* fill,
                               int* __restrict__ colout, int E) {
    int e = blockIdx.x * blockDim.x + threadIdx.x;
    if (e < E) {
        int r = row[e];
        int p = rowptr[r] + atomicAdd(&fill[r], 1);
        colout[p] = colsrc[e];
    }
}

// ----------------------- fp32 -> split bf16 converts -----------------------

__global__ void conv_x_kernel(const float* __restrict__ x,
                              __nv_bfloat16* __restrict__ hi,
                              __nv_bfloat16* __restrict__ lo, int tot4) {
    int id = blockIdx.x * blockDim.x + threadIdx.x;
    if (id >= tot4) return;
    float4 v = ((const float4*)x)[id];
    __nv_bfloat16 h0 = __float2bfloat16(v.x), h1 = __float2bfloat16(v.y);
    __nv_bfloat16 h2 = __float2bfloat16(v.z), h3 = __float2bfloat16(v.w);
    __nv_bfloat16 l0 = __float2bfloat16(v.x - __bfloat162float(h0));
    __nv_bfloat16 l1 = __float2bfloat16(v.y - __bfloat162float(h1));
    __nv_bfloat16 l2 = __float2bfloat16(v.z - __bfloat162float(h2));
    __nv_bfloat16 l3 = __float2bfloat16(v.w - __bfloat162float(h3));
    __nv_bfloat162 hp0(h0, h1), hp1(h2, h3), lp0(l0, l1), lp1(l2, l3);
    uint2 hv, lv;
    hv.x = *(uint32_t*)&hp0; hv.y = *(uint32_t*)&hp1;
    lv.x = *(uint32_t*)&lp0; lv.y = *(uint32_t*)&lp1;
    ((uint2*)hi)[id] = hv;
    ((uint2*)lo)[id] = lv;
}

// W[k][n] row-major -> Wt[y][n][k] split bf16 (B operand is [N,K] K-major)
__global__ void conv_w_kernel(const float* __restrict__ W0, const float* __restrict__ W1,
                              const float* __restrict__ W2,
                              __nv_bfloat16* __restrict__ hi, __nv_bfloat16* __restrict__ lo,
                              int K, int Nn) {
    int id = blockIdx.x * blockDim.x + threadIdx.x;
    int tot = 3 * K * Nn;
    if (id >= tot) return;
    int y = id / (K * Nn);
    int rem = id - y * K * Nn;
    int k = rem / Nn;
    int n = rem - k * Nn;
    const float* W = (y == 0) ? W0 : (y == 1) ? W1 : W2;
    float w = W[k * Nn + n];
    __nv_bfloat16 h = __float2bfloat16(w);
    __nv_bfloat16 l = __float2bfloat16(w - __bfloat162float(h));
    hi[(size_t)y * Nn * K + n * K + k] = h;
    lo[(size_t)y * Nn * K + n * K + k] = l;
}

// ------------------------- mma.sync GEMM -----------------------------------
// C = A[M,128] @ W (B[NB,128] K-major), split-bf16, fp32 accumulate.
// blockIdx.y: 0=low, 1=high, 2=mlp (relu).
// 8 warps: 2 warp-rows (64 M each) x 4 warp-cols (NB/4 each).

template <int NB>
__global__ __launch_bounds__(256, 1)
void gemm_mma(const __nv_bfloat16* __restrict__ Ahi, const __nv_bfloat16* __restrict__ Alo,
              const __nv_bfloat16* __restrict__ Bhi, const __nv_bfloat16* __restrict__ Blo,
              float* __restrict__ C0, float* __restrict__ C1, float* __restrict__ C2,
              int M) {
    constexpr int SA = 136;          // smem row stride in bf16 (272 B, conflict-free)
    constexpr int WN = NB / 4;       // warp tile N
    constexpr int NT = WN / 8;       // 8-wide n tiles per warp (4 or 2)

    extern __shared__ __align__(16) char smem[];
    __nv_bfloat16* sAhi = (__nv_bfloat16*)smem;     // 128 * SA
    __nv_bfloat16* sAlo = sAhi + 128 * SA;
    __nv_bfloat16* sBhi = sAlo + 128 * SA;          // NB * SA
    __nv_bfloat16* sBlo = sBhi + NB * SA;

    const int tid = threadIdx.x, wid = tid >> 5, lane = tid & 31;
    const int y = blockIdx.y;
    const int rowBase = blockIdx.x * 128;
    const __nv_bfloat16* bh = Bhi + (size_t)y * NB * 128;
    const __nv_bfloat16* bl = Blo + (size_t)y * NB * 128;

    // stage A (hi+lo) 128x128
    #pragma unroll
    for (int i = tid; i < 128 * 16; i += 256) {
        int r = i >> 4, c = i & 15;
        int gr = rowBase + r;
        uint4 vh = make_uint4(0, 0, 0, 0), vl = make_uint4(0, 0, 0, 0);
        if (gr < M) {
            vh = *(const uint4*)(Ahi + (size_t)gr * 128 + c * 8);
            vl = *(const uint4*)(Alo + (size_t)gr * 128 + c * 8);
        }
        *(uint4*)(sAhi + r * SA + c * 8) = vh;
        *(uint4*)(sAlo + r * SA + c * 8) = vl;
    }
    // stage B (hi+lo) NBx128
    #pragma unroll
    for (int i = tid; i < NB * 16; i += 256) {
        int r = i >> 4, c = i & 15;
        *(uint4*)(sBhi + r * SA + c * 8) = *(const uint4*)(bh + r * 128 + c * 8);
        *(uint4*)(sBlo + r * SA + c * 8) = *(const uint4*)(bl + r * 128 + c * 8);
    }
    __syncthreads();

    const int m0 = (wid >> 2) * 64;
    const int n0 = (wid & 3) * WN;

    float acc[4][NT][4];
    #pragma unroll
    for (int mt = 0; mt < 4; mt++)
        #pragma unroll
        for (int nt = 0; nt < NT; nt++)
            #pragma unroll
            for (int j = 0; j < 4; j++) acc[mt][nt][j] = 0.0f;

    const __nv_bfloat16* pA[3] = {sAhi, sAhi, sAlo};
    const __nv_bfloat16* pB[3] = {sBhi, sBlo, sBhi};

    // lane-dependent offsets for ldmatrix
    const int aj = lane >> 3;                 // matrix index 0..3
    const int aRow = ((aj & 1) << 3) + (lane & 7);
    const int aK = (aj >> 1) << 3;
    const int bRow = lane & 7;
    const int bK = ((lane >> 3) & 1) << 3;

    #pragma unroll
    for (int p = 0; p < 3; p++) {
        const uint32_t aBase = smem_u32(pA[p]);
        const uint32_t bBase = smem_u32(pB[p]);
        #pragma unroll
        for (int ks = 0; ks < 8; ks++) {
            const int k0 = ks * 16;
            uint32_t af[4][4];
            #pragma unroll
            for (int mt = 0; mt < 4; mt++) {
                uint32_t addr = aBase + (uint32_t)(((m0 + mt * 16 + aRow) * SA + k0 + aK) * 2);
                asm volatile("ldmatrix.sync.aligned.m8n8.x4.shared.b16 {%0,%1,%2,%3}, [%4];"
                             : "=r"(af[mt][0]), "=r"(af[mt][1]), "=r"(af[mt][2]), "=r"(af[mt][3])
                             : "r"(addr));
            }
            uint32_t bf[NT][2];
            #pragma unroll
            for (int nt = 0; nt < NT; nt++) {
                uint32_t addr = bBase + (uint32_t)(((n0 + nt * 8 + bRow) * SA + k0 + bK) * 2);
                asm volatile("ldmatrix.sync.aligned.m8n8.x2.shared.b16 {%0,%1}, [%2];"
                             : "=r"(bf[nt][0]), "=r"(bf[nt][1]) : "r"(addr));
            }
            #pragma unroll
            for (int mt = 0; mt < 4; mt++)
                #pragma unroll
                for (int nt = 0; nt < NT; nt++)
                    asm volatile(
                        "mma.sync.aligned.m16n8k16.row.col.f32.bf16.bf16.f32 "
                        "{%0,%1,%2,%3}, {%4,%5,%6,%7}, {%8,%9}, {%0,%1,%2,%3};"
                        : "+f"(acc[mt][nt][0]), "+f"(acc[mt][nt][1]),
                          "+f"(acc[mt][nt][2]), "+f"(acc[mt][nt][3])
                        : "r"(af[mt][0]), "r"(af[mt][1]), "r"(af[mt][2]), "r"(af[mt][3]),
                          "r"(bf[nt][0]), "r"(bf[nt][1]));
        }
    }

    // epilogue
    const bool relu = (y == 2);
    float* C = (y == 0) ? C0 : (y == 1) ? C1 : C2;
    const int colBase = n0 + (lane & 3) * 2;
    const int rTop = rowBase + m0 + (lane >> 2);
    #pragma unroll
    for (int mt = 0; mt < 4; mt++) {
        int r0 = rTop + mt * 16;
        int r1 = r0 + 8;
        #pragma unroll
        for (int nt = 0; nt < NT; nt++) {
            float2 v0, v1;
            v0.x = acc[mt][nt][0]; v0.y = acc[mt][nt][1];
            v1.x = acc[mt][nt][2]; v1.y = acc[mt][nt][3];
            if (relu) {
                v0.x = fmaxf(v0.x, 0.f); v0.y = fmaxf(v0.y, 0.f);
                v1.x = fmaxf(v1.x, 0.f); v1.y = fmaxf(v1.y, 0.f);
            }
            int c = colBase + nt * 8;
            if (r0 < M) *(float2*)(C + (size_t)r0 * NB + c) = v0;
            if (r1 < M) *(float2*)(C + (size_t)r1 * NB + c) = v1;
        }
    }
}

// ------------------- fused spmm + attention epilogue -----------------------

template <int D, bool FRELU>
__global__ __launch_bounds__(256)
void acm_fuse(const float* __restrict__ hl, const float* __restrict__ hh,
              const float* __restrict__ hm,
              const int* __restrict__ rowptr, const int* __restrict__ col,
              const float* __restrict__ vl, const float* __restrict__ vh,
              const float* __restrict__ vm, const float* __restrict__ av,
              float* __restrict__ out, int n) {
    constexpr int V = D / 32;
    int gw = (blockIdx.x * blockDim.x + threadIdx.x) >> 5;
    if (gw >= n) return;
    const int lane = threadIdx.x & 31;
    const int s = rowptr[gw], e = rowptr[gw + 1];

    float accl[V], acch[V];
    #pragma unroll
    for (int i = 0; i < V; i++) { accl[i] = 0.f; acch[i] = 0.f; }

    for (int base = s; base < e; base += 32) {
        int idx = base + lane;
        int c = (idx < e) ? col[idx] : 0;
        int cnt = min(32, e - base);
        for (int k = 0; k < cnt; k++) {
            int cc = __shfl_sync(0xffffffffu, c, k);
            const float* pl = hl + (size_t)cc * D + lane * V;
            const float* ph = hh + (size_t)cc * D + lane * V;
            if constexpr (V == 4) {
                float4 a = *(const float4*)pl;
                accl[0] += a.x; accl[1] += a.y; accl[2] += a.z; accl[3] += a.w;
                float4 b = *(const float4*)ph;
                acch[0] += b.x; acch[1] += b.y; acch[2] += b.z; acch[3] += b.w;
            } else {
                float2 a = *(const float2*)pl;
                accl[0] += a.x; accl[1] += a.y;
                float2 b = *(const float2*)ph;
                acch[0] += b.x; acch[1] += b.y;
            }
        }
    }

    const float inv = (e > s) ? 1.0f / (float)(e - s) : 0.0f;

    float low[V], high[V], mlp[V];
    {
        const float* ph = hh + (size_t)gw * D + lane * V;
        const float* pm = hm + (size_t)gw * D + lane * V;
        if constexpr (V == 4) {
            float4 b = *(const float4*)ph;
            float4 m = *(const float4*)pm;
            float hrow[4] = {b.x, b.y, b.z, b.w};
            float mrow[4] = {m.x, m.y, m.z, m.w};
            #pragma unroll
            for (int i = 0; i < 4; i++) {
                low[i]  = fmaxf(inv * accl[i], 0.f);
                high[i] = fmaxf(hrow[i] - inv * acch[i], 0.f);
                mlp[i]  = mrow[i];
            }
        } else {
            float2 b = *(const float2*)ph;
            float2 m = *(const float2*)pm;
            float hrow[2] = {b.x, b.y};
            float mrow[2] = {m.x, m.y};
            #pragma unroll
            for (int i = 0; i < 2; i++) {
                low[i]  = fmaxf(inv * accl[i], 0.f);
                high[i] = fmaxf(hrow[i] - inv * acch[i], 0.f);
                mlp[i]  = mrow[i];
            }
        }
    }

    float dl = 0.f, dh = 0.f, dm = 0.f;
    #pragma unroll
    for (int i = 0; i < V; i++) {
        dl += low[i]  * vl[lane * V + i];
        dh += high[i] * vh[lane * V + i];
        dm += mlp[i]  * vm[lane * V + i];
    }
    #pragma unroll
    for (int o = 16; o > 0; o >>= 1) {
        dl += __shfl_xor_sync(0xffffffffu, dl, o);
        dh += __shfl_xor_sync(0xffffffffu, dh, o);
        dm += __shfl_xor_sync(0xffffffffu, dm, o);
    }

    float sl = 1.0f / (1.0f + __expf(-dl));
    float sh = 1.0f / (1.0f + __expf(-dh));
    float sm = 1.0f / (1.0f + __expf(-dm));

    float t0 = (sl * av[0] + sh * av[3] + sm * av[6]) * (1.0f / 3.0f);
    float t1 = (sl * av[1] + sh * av[4] + sm * av[7]) * (1.0f / 3.0f);
    float t2 = (sl * av[2] + sh * av[5] + sm * av[8]) * (1.0f / 3.0f);
    float mx = fmaxf(t0, fmaxf(t1, t2));
    float w0 = __expf(t0 - mx), w1 = __expf(t1 - mx), w2 = __expf(t2 - mx);
    float wsum = w0 + w1 + w2;
    float a0 = 3.0f * w0 / wsum, a1 = 3.0f * w1 / wsum, a2 = 3.0f * w2 / wsum;

    float* po = out + (size_t)gw * D + lane * V;
    if constexpr (V == 4) {
        float4 o4;
        float tmp[4];
        #pragma unroll
        for (int i = 0; i < 4; i++) {
            float v = a0 * low[i] + a1 * high[i] + a2 * mlp[i];
            if (FRELU) v = fmaxf(v, 0.f);
            tmp[i] = v;
        }
        o4.x = tmp[0]; o4.y = tmp[1]; o4.z = tmp[2]; o4.w = tmp[3];
        *(float4*)po = o4;
    } else {
        float2 o2;
        float v0 = a0 * low[0] + a1 * high[0] + a2 * mlp[0];
        float v1 = a0 * low[1] + a1 * high[1] + a2 * mlp[1];
        if (FRELU) { v0 = fmaxf(v0, 0.f); v1 = fmaxf(v1, 0.f); }
        o2.x = v0; o2.y = v1;
        *(float2*)po = o2;
    }
}

// ------------------------------ launch -------------------------------------

extern "C" void kernel_launch(void* const* d_in, const int* in_sizes, int n_in,
                              void* d_out, int out_size) {
    const float* x    = (const float*)d_in[0];
    const int*   ei   = (const int*)d_in[1];
    const float* Wl1  = (const float*)d_in[2];
    const float* Wh1  = (const float*)d_in[3];
    const float* Wm1  = (const float*)d_in[4];
    const float* vl1  = (const float*)d_in[5];
    const float* vh1  = (const float*)d_in[6];
    const float* vm1  = (const float*)d_in[7];
    const float* av1  = (const float*)d_in[8];
    const float* Wl2  = (const float*)d_in[9];
    const float* Wh2  = (const float*)d_in[10];
    const float* Wm2  = (const float*)d_in[11];
    const float* vl2  = (const float*)d_in[12];
    const float* vh2  = (const float*)d_in[13];
    const float* vm2  = (const float*)d_in[14];
    const float* av2  = (const float*)d_in[15];

    const int n = in_sizes[0] / 128;
    const int E = in_sizes[1] / 2;
    const int* row = ei;
    const int* colsrc = ei + E;

    int *deg, *fill, *rowptr, *col;
    float *hl, *hh, *hm, *fea;
    __nv_bfloat16 *ahi, *alo, *wthi, *wtlo;
    cudaGetSymbolAddress((void**)&deg, g_deg);
    cudaGetSymbolAddress((void**)&fill, g_fill);
    cudaGetSymbolAddress((void**)&rowptr, g_rowptr);
    cudaGetSymbolAddress((void**)&col, g_col);
    cudaGetSymbolAddress((void**)&hl, g_hl);
    cudaGetSymbolAddress((void**)&hh, g_hh);
    cudaGetSymbolAddress((void**)&hm, g_hm);
    cudaGetSymbolAddress((void**)&fea, g_fea);
    cudaGetSymbolAddress((void**)&ahi, g_ahi);
    cudaGetSymbolAddress((void**)&alo, g_alo);
    cudaGetSymbolAddress((void**)&wthi, g_wthi);
    cudaGetSymbolAddress((void**)&wtlo, g_wtlo);

    float* out = (float*)d_out;

    const int smem1 = (2 * 128 * 136 + 2 * 128 * 136) * 2;  // 139264
    const int smem2 = (2 * 128 * 136 + 2 * 64 * 136) * 2;   // 104448
    cudaFuncSetAttribute(gemm_mma<128>, cudaFuncAttributeMaxDynamicSharedMemorySize, smem1);
    cudaFuncSetAttribute(gemm_mma<64>, cudaFuncAttributeMaxDynamicSharedMemorySize, smem2);

    // CSR build
    zero_kernel<<<(n + 255) / 256, 256>>>(deg, fill, n);
    deg_kernel<<<(E + 255) / 256, 256>>>(row, deg, E);
    scan_kernel<<<1, 1024>>>(deg, rowptr, n);
    scatter_kernel<<<(E + 255) / 256, 256>>>(row, colsrc, rowptr, fill, col, E);

    const int gx = (n + 127) / 128;

    // ---- layer 1 ----
    conv_x_kernel<<<(n * 128 / 4 + 255) / 256, 256>>>(x, ahi, alo, n * 128 / 4);
    conv_w_kernel<<<(3 * 128 * 128 + 255) / 256, 256>>>(Wl1, Wh1, Wm1, wthi, wtlo, 128, 128);
    {
        dim3 grid(gx, 3);
        gemm_mma<128><<<grid, 256, smem1>>>(ahi, alo, wthi, wtlo, hl, hh, hm, n);
    }
    acm_fuse<128, true><<<(n + 7) / 8, 256>>>(hl, hh, hm, rowptr, col,
                                              vl1, vh1, vm1, av1, fea, n);

    // ---- layer 2 ----
    conv_x_kernel<<<(n * 128 / 4 + 255) / 256, 256>>>(fea, ahi, alo, n * 128 / 4);
    conv_w_kernel<<<(3 * 128 * 64 + 255) / 256, 256>>>(Wl2, Wh2, Wm2, wthi, wtlo, 128, 64);
    {
        dim3 grid(gx, 3);
        gemm_mma<64><<<grid, 256, smem2>>>(ahi, alo, wthi, wtlo, hl, hh, hm, n);
    }
    acm_fuse<64, false><<<(n + 7) / 8, 256>>>(hl, hh, hm, rowptr, col,
                                              vl2, vh2, vm2, av2, out, n);
}

// round 4
// speedup vs baseline: 1.3802x; 1.0660x over previous
#include <cuda_runtime.h>
#include <cuda_bf16.h>
#include <cstdint>
#include <math.h>

// ---------------------------------------------------------------------------
// ACM-GCN on GB300, round 4.
// Layer 1 restructured via  adj_low @ (h@W) == (adj_low@h) @ W :
//   spmm_cvt: hagg = inv_deg * segsum(x[col]),  hdiff = x - hagg,
//             all three of {hagg, hdiff, x} emitted as split-bf16.
//   gemm_mma: low = relu(hagg@Wl), high = relu(hdiff@Wh), mlp = relu(x@Wm)
//   att_fuse: attention combine -> fea (relu).
// Layer 2 keeps round-3 structure (64-dim gather is already minimal).
// Gathers unrolled x4 neighbors for MLP.
// ---------------------------------------------------------------------------

#define MAXN 100000
#define MAXE 1600000

__device__ int   g_deg[MAXN];
__device__ int   g_fill[MAXN];
__device__ int   g_rowptr[MAXN + 1];
__device__ int   g_col[MAXE];
__device__ float g_hl[(size_t)MAXN * 128];
__device__ float g_hh[(size_t)MAXN * 128];
__device__ float g_hm[(size_t)MAXN * 128];
__device__ float g_fea[(size_t)MAXN * 128];
__device__ __nv_bfloat16 g_ahi[(size_t)MAXN * 128];
__device__ __nv_bfloat16 g_alo[(size_t)MAXN * 128];
__device__ __nv_bfloat16 g_bhi[(size_t)MAXN * 128];
__device__ __nv_bfloat16 g_blo[(size_t)MAXN * 128];
__device__ __nv_bfloat16 g_chi[(size_t)MAXN * 128];
__device__ __nv_bfloat16 g_clo[(size_t)MAXN * 128];
__device__ __nv_bfloat16 g_wthi[3 * 128 * 128];
__device__ __nv_bfloat16 g_wtlo[3 * 128 * 128];

__device__ __forceinline__ uint32_t smem_u32(const void* p) {
    uint32_t a;
    asm("{ .reg .u64 t; cvta.to.shared.u64 t, %1; cvt.u32.u64 %0, t; }"
        : "=r"(a) : "l"(p));
    return a;
}

// --------------------------- CSR construction -----------------------------

__global__ void zero_kernel(int* deg, int* fill, int n) {
    int i = blockIdx.x * blockDim.x + threadIdx.x;
    if (i < n) { deg[i] = 0; fill[i] = 0; }
}

__global__ void deg_kernel(const int* __restrict__ row, int* deg, int E) {
    int e = blockIdx.x * blockDim.x + threadIdx.x;
    if (e < E) atomicAdd(&deg[row[e]], 1);
}

__global__ void scan_kernel(const int* __restrict__ deg, int* __restrict__ rowptr, int n) {
    __shared__ int wsum[32];
    __shared__ int carry;
    int tid = threadIdx.x, lane = tid & 31, w = tid >> 5;
    if (tid == 0) carry = 0;
    __syncthreads();
    for (int base = 0; base < n; base += 1024) {
        int i = base + tid;
        int v = (i < n) ? deg[i] : 0;
        int x = v;
        #pragma unroll
        for (int o = 1; o < 32; o <<= 1) {
            int y = __shfl_up_sync(0xffffffffu, x, o);
            if (lane >= o) x += y;
        }
        if (lane == 31) wsum[w] = x;
        __syncthreads();
        if (w == 0) {
            int t = wsum[lane];
            #pragma unroll
            for (int o = 1; o < 32; o <<= 1) {
                int y = __shfl_up_sync(0xffffffffu, t, o);
                if (lane >= o) t += y;
            }
            wsum[lane] = t;
        }
        __syncthreads();
        int off = carry + (w > 0 ? wsum[w - 1] : 0);
        if (i < n) rowptr[i] = off + x - v;
        int blocktotal = wsum[31];
        __syncthreads();
        if (tid == 0) carry += blocktotal;
        __syncthreads();
    }
    if (threadIdx.x == 0) rowptr[n] = carry;
}

__global__ void scatter_kernel(const int* __restrict__ row, const int* __restrict__ colsrc,
                               const int* __restrict__ rowptr, int* fill,
                               int* __restrict__ colout, int E) {
    int e = blockIdx.x * blockDim.x + threadIdx.x;
    if (e < E) {
        int r = row[e];
        int p = rowptr[r] + atomicAdd(&fill[r], 1);
        colout[p] = colsrc[e];
    }
}

// ----------------------- split-bf16 helpers --------------------------------

__device__ __forceinline__ void split4(const float* v, uint2& hv, uint2& lv) {
    __nv_bfloat16 h0 = __float2bfloat16(v[0]), h1 = __float2bfloat16(v[1]);
    __nv_bfloat16 h2 = __float2bfloat16(v[2]), h3 = __float2bfloat16(v[3]);
    __nv_bfloat16 l0 = __float2bfloat16(v[0] - __bfloat162float(h0));
    __nv_bfloat16 l1 = __float2bfloat16(v[1] - __bfloat162float(h1));
    __nv_bfloat16 l2 = __float2bfloat16(v[2] - __bfloat162float(h2));
    __nv_bfloat16 l3 = __float2bfloat16(v[3] - __bfloat162float(h3));
    __nv_bfloat162 hp0(h0, h1), hp1(h2, h3), lp0(l0, l1), lp1(l2, l3);
    hv.x = *(uint32_t*)&hp0; hv.y = *(uint32_t*)&hp1;
    lv.x = *(uint32_t*)&lp0; lv.y = *(uint32_t*)&lp1;
}

__global__ void conv_x_kernel(const float* __restrict__ x,
                              __nv_bfloat16* __restrict__ hi,
                              __nv_bfloat16* __restrict__ lo, int tot4) {
    int id = blockIdx.x * blockDim.x + threadIdx.x;
    if (id >= tot4) return;
    float4 v = ((const float4*)x)[id];
    uint2 hv, lv;
    split4((const float*)&v, hv, lv);
    ((uint2*)hi)[id] = hv;
    ((uint2*)lo)[id] = lv;
}

// W[k][n] row-major -> Wt[y][n][k] split bf16
__global__ void conv_w_kernel(const float* __restrict__ W0, const float* __restrict__ W1,
                              const float* __restrict__ W2,
                              __nv_bfloat16* __restrict__ hi, __nv_bfloat16* __restrict__ lo,
                              int K, int Nn) {
    int id = blockIdx.x * blockDim.x + threadIdx.x;
    int tot = 3 * K * Nn;
    if (id >= tot) return;
    int y = id / (K * Nn);
    int rem = id - y * K * Nn;
    int k = rem / Nn;
    int n = rem - k * Nn;
    const float* W = (y == 0) ? W0 : (y == 1) ? W1 : W2;
    float w = W[k * Nn + n];
    __nv_bfloat16 h = __float2bfloat16(w);
    __nv_bfloat16 l = __float2bfloat16(w - __bfloat162float(h));
    hi[(size_t)y * Nn * K + n * K + k] = h;
    lo[(size_t)y * Nn * K + n * K + k] = l;
}

// -------------------- layer-1 spmm + split converts ------------------------
// warp per node: hagg = inv_deg * sum_{c in N(i)} x[c];  hdiff = x[i]-hagg;
// emit split-bf16 for hagg (A), hdiff (B), x (C).

__global__ __launch_bounds__(256)
void spmm_cvt(const float* __restrict__ x,
              const int* __restrict__ rowptr, const int* __restrict__ col,
              __nv_bfloat16* __restrict__ Ahi, __nv_bfloat16* __restrict__ Alo,
              __nv_bfloat16* __restrict__ Bhi, __nv_bfloat16* __restrict__ Blo,
              __nv_bfloat16* __restrict__ Chi, __nv_bfloat16* __restrict__ Clo,
              int n) {
    int gw = (blockIdx.x * blockDim.x + threadIdx.x) >> 5;
    if (gw >= n) return;
    const int lane = threadIdx.x & 31;
    const int s = rowptr[gw], e = rowptr[gw + 1];

    float acc[4] = {0.f, 0.f, 0.f, 0.f};

    for (int base = s; base < e; base += 32) {
        int idx = base + lane;
        int c = (idx < e) ? col[idx] : 0;
        int cnt = min(32, e - base);
        int k = 0;
        for (; k + 4 <= cnt; k += 4) {
            int c0 = __shfl_sync(0xffffffffu, c, k);
            int c1 = __shfl_sync(0xffffffffu, c, k + 1);
            int c2 = __shfl_sync(0xffffffffu, c, k + 2);
            int c3 = __shfl_sync(0xffffffffu, c, k + 3);
            float4 v0 = *(const float4*)(x + (size_t)c0 * 128 + lane * 4);
            float4 v1 = *(const float4*)(x + (size_t)c1 * 128 + lane * 4);
            float4 v2 = *(const float4*)(x + (size_t)c2 * 128 + lane * 4);
            float4 v3 = *(const float4*)(x + (size_t)c3 * 128 + lane * 4);
            acc[0] += v0.x + v1.x + v2.x + v3.x;
            acc[1] += v0.y + v1.y + v2.y + v3.y;
            acc[2] += v0.z + v1.z + v2.z + v3.z;
            acc[3] += v0.w + v1.w + v2.w + v3.w;
        }
        for (; k < cnt; k++) {
            int cc = __shfl_sync(0xffffffffu, c, k);
            float4 v = *(const float4*)(x + (size_t)cc * 128 + lane * 4);
            acc[0] += v.x; acc[1] += v.y; acc[2] += v.z; acc[3] += v.w;
        }
    }

    const float inv = (e > s) ? 1.0f / (float)(e - s) : 0.0f;
    float4 hrow = *(const float4*)(x + (size_t)gw * 128 + lane * 4);

    float agg[4], dif[4], own[4] = {hrow.x, hrow.y, hrow.z, hrow.w};
    #pragma unroll
    for (int i = 0; i < 4; i++) {
        agg[i] = inv * acc[i];
        dif[i] = own[i] - agg[i];
    }

    const size_t off = ((size_t)gw * 128 + lane * 4) / 4;  // uint2 index
    uint2 hv, lv;
    split4(agg, hv, lv); ((uint2*)Ahi)[off] = hv; ((uint2*)Alo)[off] = lv;
    split4(dif, hv, lv); ((uint2*)Bhi)[off] = hv; ((uint2*)Blo)[off] = lv;
    split4(own, hv, lv); ((uint2*)Chi)[off] = hv; ((uint2*)Clo)[off] = lv;
}

// ------------------------- mma.sync GEMM -----------------------------------
// C = A[y][M,128] @ W[y] (B[NB,128] K-major), split-bf16, fp32 accumulate.
// reluAll: relu every branch (layer 1); else only y==2.

template <int NB>
__global__ __launch_bounds__(256, 1)
void gemm_mma(const __nv_bfloat16* __restrict__ A0hi, const __nv_bfloat16* __restrict__ A0lo,
              const __nv_bfloat16* __restrict__ A1hi, const __nv_bfloat16* __restrict__ A1lo,
              const __nv_bfloat16* __restrict__ A2hi, const __nv_bfloat16* __restrict__ A2lo,
              const __nv_bfloat16* __restrict__ Bhi, const __nv_bfloat16* __restrict__ Blo,
              float* __restrict__ C0, float* __restrict__ C1, float* __restrict__ C2,
              int M, int reluAll) {
    constexpr int SA = 136;
    constexpr int WN = NB / 4;
    constexpr int NT = WN / 8;

    extern __shared__ __align__(16) char smem[];
    __nv_bfloat16* sAhi = (__nv_bfloat16*)smem;
    __nv_bfloat16* sAlo = sAhi + 128 * SA;
    __nv_bfloat16* sBhi = sAlo + 128 * SA;
    __nv_bfloat16* sBlo = sBhi + NB * SA;

    const int tid = threadIdx.x, wid = tid >> 5, lane = tid & 31;
    const int y = blockIdx.y;
    const int rowBase = blockIdx.x * 128;
    const __nv_bfloat16* Ahi = (y == 0) ? A0hi : (y == 1) ? A1hi : A2hi;
    const __nv_bfloat16* Alo = (y == 0) ? A0lo : (y == 1) ? A1lo : A2lo;
    const __nv_bfloat16* bh = Bhi + (size_t)y * NB * 128;
    const __nv_bfloat16* bl = Blo + (size_t)y * NB * 128;

    #pragma unroll
    for (int i = tid; i < 128 * 16; i += 256) {
        int r = i >> 4, c = i & 15;
        int gr = rowBase + r;
        uint4 vh = make_uint4(0, 0, 0, 0), vl = make_uint4(0, 0, 0, 0);
        if (gr < M) {
            vh = *(const uint4*)(Ahi + (size_t)gr * 128 + c * 8);
            vl = *(const uint4*)(Alo + (size_t)gr * 128 + c * 8);
        }
        *(uint4*)(sAhi + r * SA + c * 8) = vh;
        *(uint4*)(sAlo + r * SA + c * 8) = vl;
    }
    #pragma unroll
    for (int i = tid; i < NB * 16; i += 256) {
        int r = i >> 4, c = i & 15;
        *(uint4*)(sBhi + r * SA + c * 8) = *(const uint4*)(bh + r * 128 + c * 8);
        *(uint4*)(sBlo + r * SA + c * 8) = *(const uint4*)(bl + r * 128 + c * 8);
    }
    __syncthreads();

    const int m0 = (wid >> 2) * 64;
    const int n0 = (wid & 3) * WN;

    float acc[4][NT][4];
    #pragma unroll
    for (int mt = 0; mt < 4; mt++)
        #pragma unroll
        for (int nt = 0; nt < NT; nt++)
            #pragma unroll
            for (int j = 0; j < 4; j++) acc[mt][nt][j] = 0.0f;

    const __nv_bfloat16* pA[3] = {sAhi, sAhi, sAlo};
    const __nv_bfloat16* pB[3] = {sBhi, sBlo, sBhi};

    const int aj = lane >> 3;
    const int aRow = ((aj & 1) << 3) + (lane & 7);
    const int aK = (aj >> 1) << 3;
    const int bRow = lane & 7;
    const int bK = ((lane >> 3) & 1) << 3;

    #pragma unroll
    for (int p = 0; p < 3; p++) {
        const uint32_t aBase = smem_u32(pA[p]);
        const uint32_t bBase = smem_u32(pB[p]);
        #pragma unroll
        for (int ks = 0; ks < 8; ks++) {
            const int k0 = ks * 16;
            uint32_t af[4][4];
            #pragma unroll
            for (int mt = 0; mt < 4; mt++) {
                uint32_t addr = aBase + (uint32_t)(((m0 + mt * 16 + aRow) * SA + k0 + aK) * 2);
                asm volatile("ldmatrix.sync.aligned.m8n8.x4.shared.b16 {%0,%1,%2,%3}, [%4];"
                             : "=r"(af[mt][0]), "=r"(af[mt][1]), "=r"(af[mt][2]), "=r"(af[mt][3])
                             : "r"(addr));
            }
            uint32_t bf[NT][2];
            #pragma unroll
            for (int nt = 0; nt < NT; nt++) {
                uint32_t addr = bBase + (uint32_t)(((n0 + nt * 8 + bRow) * SA + k0 + bK) * 2);
                asm volatile("ldmatrix.sync.aligned.m8n8.x2.shared.b16 {%0,%1}, [%2];"
                             : "=r"(bf[nt][0]), "=r"(bf[nt][1]) : "r"(addr));
            }
            #pragma unroll
            for (int mt = 0; mt < 4; mt++)
                #pragma unroll
                for (int nt = 0; nt < NT; nt++)
                    asm volatile(
                        "mma.sync.aligned.m16n8k16.row.col.f32.bf16.bf16.f32 "
                        "{%0,%1,%2,%3}, {%4,%5,%6,%7}, {%8,%9}, {%0,%1,%2,%3};"
                        : "+f"(acc[mt][nt][0]), "+f"(acc[mt][nt][1]),
                          "+f"(acc[mt][nt][2]), "+f"(acc[mt][nt][3])
                        : "r"(af[mt][0]), "r"(af[mt][1]), "r"(af[mt][2]), "r"(af[mt][3]),
                          "r"(bf[nt][0]), "r"(bf[nt][1]));
        }
    }

    const bool relu = reluAll || (y == 2);
    float* C = (y == 0) ? C0 : (y == 1) ? C1 : C2;
    const int colBase = n0 + (lane & 3) * 2;
    const int rTop = rowBase + m0 + (lane >> 2);
    #pragma unroll
    for (int mt = 0; mt < 4; mt++) {
        int r0 = rTop + mt * 16;
        int r1 = r0 + 8;
        #pragma unroll
        for (int nt = 0; nt < NT; nt++) {
            float2 v0, v1;
            v0.x = acc[mt][nt][0]; v0.y = acc[mt][nt][1];
            v1.x = acc[mt][nt][2]; v1.y = acc[mt][nt][3];
            if (relu) {
                v0.x = fmaxf(v0.x, 0.f); v0.y = fmaxf(v0.y, 0.f);
                v1.x = fmaxf(v1.x, 0.f); v1.y = fmaxf(v1.y, 0.f);
            }
            int c = colBase + nt * 8;
            if (r0 < M) *(float2*)(C + (size_t)r0 * NB + c) = v0;
            if (r1 < M) *(float2*)(C + (size_t)r1 * NB + c) = v1;
        }
    }
}

// ------------------- layer-1 attention combine (elementwise) ---------------
// warp per node: read low/high/mlp rows (128), attention, relu, write fea.

__global__ __launch_bounds__(256)
void att_fuse(const float* __restrict__ ol, const float* __restrict__ oh,
              const float* __restrict__ om,
              const float* __restrict__ vl, const float* __restrict__ vh,
              const float* __restrict__ vm, const float* __restrict__ av,
              float* __restrict__ out, int n) {
    int gw = (blockIdx.x * blockDim.x + threadIdx.x) >> 5;
    if (gw >= n) return;
    const int lane = threadIdx.x & 31;
    const size_t base = (size_t)gw * 128 + lane * 4;

    float4 lo4 = *(const float4*)(ol + base);
    float4 hi4 = *(const float4*)(oh + base);
    float4 ml4 = *(const float4*)(om + base);
    float low[4] = {lo4.x, lo4.y, lo4.z, lo4.w};
    float high[4] = {hi4.x, hi4.y, hi4.z, hi4.w};
    float mlp[4] = {ml4.x, ml4.y, ml4.z, ml4.w};

    float dl = 0.f, dh = 0.f, dm = 0.f;
    #pragma unroll
    for (int i = 0; i < 4; i++) {
        dl += low[i]  * vl[lane * 4 + i];
        dh += high[i] * vh[lane * 4 + i];
        dm += mlp[i]  * vm[lane * 4 + i];
    }
    #pragma unroll
    for (int o = 16; o > 0; o >>= 1) {
        dl += __shfl_xor_sync(0xffffffffu, dl, o);
        dh += __shfl_xor_sync(0xffffffffu, dh, o);
        dm += __shfl_xor_sync(0xffffffffu, dm, o);
    }

    float sl = 1.0f / (1.0f + __expf(-dl));
    float sh = 1.0f / (1.0f + __expf(-dh));
    float sm = 1.0f / (1.0f + __expf(-dm));

    float t0 = (sl * av[0] + sh * av[3] + sm * av[6]) * (1.0f / 3.0f);
    float t1 = (sl * av[1] + sh * av[4] + sm * av[7]) * (1.0f / 3.0f);
    float t2 = (sl * av[2] + sh * av[5] + sm * av[8]) * (1.0f / 3.0f);
    float mx = fmaxf(t0, fmaxf(t1, t2));
    float w0 = __expf(t0 - mx), w1 = __expf(t1 - mx), w2 = __expf(t2 - mx);
    float wsum = w0 + w1 + w2;
    float a0 = 3.0f * w0 / wsum, a1 = 3.0f * w1 / wsum, a2 = 3.0f * w2 / wsum;

    float4 o4;
    float tmp[4];
    #pragma unroll
    for (int i = 0; i < 4; i++)
        tmp[i] = fmaxf(a0 * low[i] + a1 * high[i] + a2 * mlp[i], 0.f);
    o4.x = tmp[0]; o4.y = tmp[1]; o4.z = tmp[2]; o4.w = tmp[3];
    *(float4*)(out + base) = o4;
}

// ------------- layer-2 fused spmm + attention (round-3 style, D=64) --------

__global__ __launch_bounds__(256)
void acm_fuse64(const float* __restrict__ hl, const float* __restrict__ hh,
                const float* __restrict__ hm,
                const int* __restrict__ rowptr, const int* __restrict__ col,
                const float* __restrict__ vl, const float* __restrict__ vh,
                const float* __restrict__ vm, const float* __restrict__ av,
                float* __restrict__ out, int n) {
    constexpr int D = 64;
    int gw = (blockIdx.x * blockDim.x + threadIdx.x) >> 5;
    if (gw >= n) return;
    const int lane = threadIdx.x & 31;
    const int s = rowptr[gw], e = rowptr[gw + 1];

    float accl[2] = {0.f, 0.f}, acch[2] = {0.f, 0.f};

    for (int base = s; base < e; base += 32) {
        int idx = base + lane;
        int c = (idx < e) ? col[idx] : 0;
        int cnt = min(32, e - base);
        int k = 0;
        for (; k + 4 <= cnt; k += 4) {
            int c0 = __shfl_sync(0xffffffffu, c, k);
            int c1 = __shfl_sync(0xffffffffu, c, k + 1);
            int c2 = __shfl_sync(0xffffffffu, c, k + 2);
            int c3 = __shfl_sync(0xffffffffu, c, k + 3);
            float2 a0 = *(const float2*)(hl + (size_t)c0 * D + lane * 2);
            float2 a1 = *(const float2*)(hl + (size_t)c1 * D + lane * 2);
            float2 a2 = *(const float2*)(hl + (size_t)c2 * D + lane * 2);
            float2 a3 = *(const float2*)(hl + (size_t)c3 * D + lane * 2);
            float2 b0 = *(const float2*)(hh + (size_t)c0 * D + lane * 2);
            float2 b1 = *(const float2*)(hh + (size_t)c1 * D + lane * 2);
            float2 b2 = *(const float2*)(hh + (size_t)c2 * D + lane * 2);
            float2 b3 = *(const float2*)(hh + (size_t)c3 * D + lane * 2);
            accl[0] += a0.x + a1.x + a2.x + a3.x;
            accl[1] += a0.y + a1.y + a2.y + a3.y;
            acch[0] += b0.x + b1.x + b2.x + b3.x;
            acch[1] += b0.y + b1.y + b2.y + b3.y;
        }
        for (; k < cnt; k++) {
            int cc = __shfl_sync(0xffffffffu, c, k);
            float2 a = *(const float2*)(hl + (size_t)cc * D + lane * 2);
            float2 b = *(const float2*)(hh + (size_t)cc * D + lane * 2);
            accl[0] += a.x; accl[1] += a.y;
            acch[0] += b.x; acch[1] += b.y;
        }
    }

    const float inv = (e > s) ? 1.0f / (float)(e - s) : 0.0f;

    float2 b = *(const float2*)(hh + (size_t)gw * D + lane * 2);
    float2 m = *(const float2*)(hm + (size_t)gw * D + lane * 2);
    float hrow[2] = {b.x, b.y};
    float mrow[2] = {m.x, m.y};
    float low[2], high[2], mlp[2];
    #pragma unroll
    for (int i = 0; i < 2; i++) {
        low[i]  = fmaxf(inv * accl[i], 0.f);
        high[i] = fmaxf(hrow[i] - inv * acch[i], 0.f);
        mlp[i]  = mrow[i];
    }

    float dl = 0.f, dh = 0.f, dm = 0.f;
    #pragma unroll
    for (int i = 0; i < 2; i++) {
        dl += low[i]  * vl[lane * 2 + i];
        dh += high[i] * vh[lane * 2 + i];
        dm += mlp[i]  * vm[lane * 2 + i];
    }
    #pragma unroll
    for (int o = 16; o > 0; o >>= 1) {
        dl += __shfl_xor_sync(0xffffffffu, dl, o);
        dh += __shfl_xor_sync(0xffffffffu, dh, o);
        dm += __shfl_xor_sync(0xffffffffu, dm, o);
    }

    float sl = 1.0f / (1.0f + __expf(-dl));
    float sh = 1.0f / (1.0f + __expf(-dh));
    float sm = 1.0f / (1.0f + __expf(-dm));

    float t0 = (sl * av[0] + sh * av[3] + sm * av[6]) * (1.0f / 3.0f);
    float t1 = (sl * av[1] + sh * av[4] + sm * av[7]) * (1.0f / 3.0f);
    float t2 = (sl * av[2] + sh * av[5] + sm * av[8]) * (1.0f / 3.0f);
    float mx = fmaxf(t0, fmaxf(t1, t2));
    float w0 = __expf(t0 - mx), w1 = __expf(t1 - mx), w2 = __expf(t2 - mx);
    float wsum = w0 + w1 + w2;
    float a0 = 3.0f * w0 / wsum, a1 = 3.0f * w1 / wsum, a2 = 3.0f * w2 / wsum;

    float2 o2;
    o2.x = a0 * low[0] + a1 * high[0] + a2 * mlp[0];
    o2.y = a0 * low[1] + a1 * high[1] + a2 * mlp[1];
    *(float2*)(out + (size_t)gw * D + lane * 2) = o2;
}

// ------------------------------ launch -------------------------------------

extern "C" void kernel_launch(void* const* d_in, const int* in_sizes, int n_in,
                              void* d_out, int out_size) {
    const float* x    = (const float*)d_in[0];
    const int*   ei   = (const int*)d_in[1];
    const float* Wl1  = (const float*)d_in[2];
    const float* Wh1  = (const float*)d_in[3];
    const float* Wm1  = (const float*)d_in[4];
    const float* vl1  = (const float*)d_in[5];
    const float* vh1  = (const float*)d_in[6];
    const float* vm1  = (const float*)d_in[7];
    const float* av1  = (const float*)d_in[8];
    const float* Wl2  = (const float*)d_in[9];
    const float* Wh2  = (const float*)d_in[10];
    const float* Wm2  = (const float*)d_in[11];
    const float* vl2  = (const float*)d_in[12];
    const float* vh2  = (const float*)d_in[13];
    const float* vm2  = (const float*)d_in[14];
    const float* av2  = (const float*)d_in[15];

    const int n = in_sizes[0] / 128;
    const int E = in_sizes[1] / 2;
    const int* row = ei;
    const int* colsrc = ei + E;

    int *deg, *fill, *rowptr, *col;
    float *hl, *hh, *hm, *fea;
    __nv_bfloat16 *ahi, *alo, *bhi, *blo, *chi, *clo, *wthi, *wtlo;
    cudaGetSymbolAddress((void**)&deg, g_deg);
    cudaGetSymbolAddress((void**)&fill, g_fill);
    cudaGetSymbolAddress((void**)&rowptr, g_rowptr);
    cudaGetSymbolAddress((void**)&col, g_col);
    cudaGetSymbolAddress((void**)&hl, g_hl);
    cudaGetSymbolAddress((void**)&hh, g_hh);
    cudaGetSymbolAddress((void**)&hm, g_hm);
    cudaGetSymbolAddress((void**)&fea, g_fea);
    cudaGetSymbolAddress((void**)&ahi, g_ahi);
    cudaGetSymbolAddress((void**)&alo, g_alo);
    cudaGetSymbolAddress((void**)&bhi, g_bhi);
    cudaGetSymbolAddress((void**)&blo, g_blo);
    cudaGetSymbolAddress((void**)&chi, g_chi);
    cudaGetSymbolAddress((void**)&clo, g_clo);
    cudaGetSymbolAddress((void**)&wthi, g_wthi);
    cudaGetSymbolAddress((void**)&wtlo, g_wtlo);

    float* out = (float*)d_out;

    const int smem1 = (2 * 128 * 136 + 2 * 128 * 136) * 2;
    const int smem2 = (2 * 128 * 136 + 2 * 64 * 136) * 2;
    cudaFuncSetAttribute(gemm_mma<128>, cudaFuncAttributeMaxDynamicSharedMemorySize, smem1);
    cudaFuncSetAttribute(gemm_mma<64>, cudaFuncAttributeMaxDynamicSharedMemorySize, smem2);

    // CSR build
    zero_kernel<<<(n + 255) / 256, 256>>>(deg, fill, n);
    deg_kernel<<<(E + 255) / 256, 256>>>(row, deg, E);
    scan_kernel<<<1, 1024>>>(deg, rowptr, n);
    scatter_kernel<<<(E + 255) / 256, 256>>>(row, colsrc, rowptr, fill, col, E);

    const int gx = (n + 127) / 128;

    // ---- layer 1 (restructured) ----
    conv_w_kernel<<<(3 * 128 * 128 + 255) / 256, 256>>>(Wl1, Wh1, Wm1, wthi, wtlo, 128, 128);
    spmm_cvt<<<(n + 7) / 8, 256>>>(x, rowptr, col, ahi, alo, bhi, blo, chi, clo, n);
    {
        dim3 grid(gx, 3);
        gemm_mma<128><<<grid, 256, smem1>>>(ahi, alo, bhi, blo, chi, clo,
                                            wthi, wtlo, hl, hh, hm, n, 1);
    }
    att_fuse<<<(n + 7) / 8, 256>>>(hl, hh, hm, vl1, vh1, vm1, av1, fea, n);

    // ---- layer 2 (round-3 style) ----
    conv_x_kernel<<<(n * 128 / 4 + 255) / 256, 256>>>(fea, ahi, alo, n * 128 / 4);
    conv_w_kernel<<<(3 * 128 * 64 + 255) / 256, 256>>>(Wl2, Wh2, Wm2, wthi, wtlo, 128, 64);
    {
        dim3 grid(gx, 3);
        gemm_mma<64><<<grid, 256, smem2>>>(ahi, alo, ahi, alo, ahi, alo,
                                           wthi, wtlo, hl, hh, hm, n, 0);
    }
    acm_fuse64<<<(n + 7) / 8, 256>>>(hl, hh, hm, rowptr, col,
                                     vl2, vh2, vm2, av2, out, n);
}